// round 4
// baseline (speedup 1.0000x reference)
#include <cuda_runtime.h>
#include <cuda_bf16.h>

// GradPooling: out[b,oh,ow,c] = sel ? max2x2 : mean2x2
//   sel     = 2*(|x[oh+1,ow+1]-x[oh,ow+1]| + |x[oh+1,ow+1]-x[oh+1,ow]|) > lamb
//   window  = x rows {2oh-1, 2oh} x cols {2ow-1, 2ow}, OOB (index -1) -> 0.0
//             (zero participates in max; mean divisor fixed at 4)
// Shapes: x (32,224,224,64) f32 NHWC, out (32,112,112,64) f32.

#define B_   32
#define H_   224
#define W_   224
#define C_   64
#define OH_  112
#define OW_  112
#define C4_  (C_ / 4)   // 16 float4 groups per pixel

__global__ __launch_bounds__(256)
void gradpool_kernel(const float* __restrict__ x,
                     const float* __restrict__ lamb,
                     float* __restrict__ out)
{
    const long long tid = (long long)blockIdx.x * blockDim.x + threadIdx.x;
    const long long total = (long long)B_ * OH_ * OW_ * C4_;
    if (tid >= total) return;

    int c4 = (int)(tid & (C4_ - 1));
    long long t = tid >> 4;            // C4_ == 16
    int ow = (int)(t % OW_);  t /= OW_;
    int oh = (int)(t % OH_);
    int b  = (int)(t / OH_);

    const float lam = __ldg(lamb);

    const float* xb = x + (long long)b * (H_ * W_ * C_);
    const int c = c4 * 4;

    // ---- gradient taps (always in-bounds: oh+1 <= 112 < 224) ----
    const float4* pc = (const float4*)(xb + ((long long)(oh + 1) * W_ + (ow + 1)) * C_ + c);
    const float4* pu = (const float4*)(xb + ((long long)(oh    ) * W_ + (ow + 1)) * C_ + c);
    const float4* pl = (const float4*)(xb + ((long long)(oh + 1) * W_ + (ow    )) * C_ + c);
    float4 ctr = *pc;
    float4 up  = *pu;
    float4 lf  = *pl;

    // ---- pool window ----
    const int h0 = 2 * oh - 1;
    const int h1 = 2 * oh;
    const int w0 = 2 * ow - 1;
    const int w1 = 2 * ow;

    const float4 z = make_float4(0.f, 0.f, 0.f, 0.f);
    float4 v00 = z, v01 = z, v10 = z, v11;
    v11 = *(const float4*)(xb + ((long long)h1 * W_ + w1) * C_ + c);
    if (w0 >= 0)           v10 = *(const float4*)(xb + ((long long)h1 * W_ + w0) * C_ + c);
    if (h0 >= 0)           v01 = *(const float4*)(xb + ((long long)h0 * W_ + w1) * C_ + c);
    if (h0 >= 0 && w0 >= 0) v00 = *(const float4*)(xb + ((long long)h0 * W_ + w0) * C_ + c);

    float4 o;
#define COMP(f)                                                               \
    {                                                                         \
        float mx = fmaxf(fmaxf(v00.f, v01.f), fmaxf(v10.f, v11.f));           \
        float mn = (v00.f + v01.f + v10.f + v11.f) * 0.25f;                   \
        float d  = 2.0f * (fabsf(ctr.f - up.f) + fabsf(ctr.f - lf.f));        \
        o.f = (d > lam) ? mx : mn;                                            \
    }
    COMP(x) COMP(y) COMP(z) COMP(w)
#undef COMP

    *(float4*)(out + tid * 4) = o;
}

extern "C" void kernel_launch(void* const* d_in, const int* in_sizes, int n_in,
                              void* d_out, int out_size)
{
    // metadata order: x, lamb — but guard on sizes (lamb has 1 element).
    const float* x    = (const float*)d_in[0];
    const float* lamb = (const float*)d_in[1];
    if (n_in >= 2 && in_sizes[0] == 1) {
        x    = (const float*)d_in[1];
        lamb = (const float*)d_in[0];
    }

    const long long total = (long long)B_ * OH_ * OW_ * C4_;  // 6,422,528 threads
    const int threads = 256;
    const int blocks = (int)((total + threads - 1) / threads);
    gradpool_kernel<<<blocks, threads>>>(x, lamb, (float*)d_out);
}

// round 5
// speedup vs baseline: 1.0413x; 1.0413x over previous
#include <cuda_runtime.h>
#include <cuda_bf16.h>

// GradPooling: out[b,oh,ow,c] = sel ? max2x2 : mean2x2
//   sel = 2*(|x[oh+1,ow+1]-x[oh,ow+1]| + |x[oh+1,ow+1]-x[oh+1,ow]|) > lamb
//   pool window = x rows {2oh-1,2oh} x cols {2ow-1,2ow}, OOB -> 0.0
//   (zero participates in max; mean divisor fixed at 4)
// x (32,224,224,64) f32 NHWC, out (32,112,112,64) f32.
//
// R4: one thread computes an ow-PAIR (pixels 2j and 2j+1) for 4 channels.
//     Right pixel's left-gradient tap == left pixel's center tap (1 load saved),
//     and per-thread MLP ~doubles (13 loads in flight) to push HBM utilization.

#define B_   32
#define H_   224
#define W_   224
#define C_   64
#define OH_  112
#define OW_  112
#define OJ_  (OW_ / 2)   // 56 ow-pairs
#define C4_  (C_ / 4)    // 16 float4 groups per pixel

__global__ __launch_bounds__(256)
void gradpool_kernel(const float* __restrict__ x,
                     const float* __restrict__ lamb,
                     float* __restrict__ out)
{
    const int tid = blockIdx.x * blockDim.x + threadIdx.x;
    const int total = B_ * OH_ * OJ_ * C4_;          // 3,211,264
    if (tid >= total) return;

    const int c4 = tid & (C4_ - 1);
    int t = tid >> 4;
    const int j  = t % OJ_;  t /= OJ_;
    const int oh = t % OH_;
    const int b  = t / OH_;

    const float lam = __ldg(lamb);

    const float4* xb = (const float4*)(x) + ((b * H_) * W_) * C4_ + c4;
    // helper: float4 at (row h, col w) of this image/channel-group
    #define XV(h, w) xb[((h) * W_ + (w)) * C4_]

    // ---- gradient taps (rows oh..oh+1 <= 112, cols 2j..2j+2 <= 112: in-bounds) ----
    const int gw = 2 * j;
    float4 upL  = XV(oh,     gw + 1);
    float4 upR  = XV(oh,     gw + 2);
    float4 lfL  = XV(oh + 1, gw);
    float4 ctrL = XV(oh + 1, gw + 1);
    float4 ctrR = XV(oh + 1, gw + 2);
    // right pixel's left tap == ctrL

    // ---- pool windows: rows {2oh-1, 2oh}, cols {4j-1, 4j} (L) and {4j+1, 4j+2} (R) ----
    const int h0 = 2 * oh - 1;
    const int h1 = 2 * oh;
    const int w0 = 4 * j - 1;

    const float4 z = make_float4(0.f, 0.f, 0.f, 0.f);
    float4 a00 = z, a01, a02, a03;          // row h0, cols w0..w0+3
    float4 b00 = z, b01, b02, b03;          // row h1
    b01 = XV(h1, w0 + 1);
    b02 = XV(h1, w0 + 2);
    b03 = XV(h1, w0 + 3);
    if (j > 0) b00 = XV(h1, w0);
    if (oh > 0) {
        a01 = XV(h0, w0 + 1);
        a02 = XV(h0, w0 + 2);
        a03 = XV(h0, w0 + 3);
        if (j > 0) a00 = XV(h0, w0);
    } else {
        a01 = z; a02 = z; a03 = z;
    }
    #undef XV

    float4 oL, oR;
#define COMP(f)                                                                \
    {                                                                          \
        float dL = 2.0f * (fabsf(ctrL.f - upL.f) + fabsf(ctrL.f - lfL.f));     \
        float mxL = fmaxf(fmaxf(a00.f, a01.f), fmaxf(b00.f, b01.f));           \
        float mnL = (a00.f + a01.f + b00.f + b01.f) * 0.25f;                   \
        oL.f = (dL > lam) ? mxL : mnL;                                         \
        float dR = 2.0f * (fabsf(ctrR.f - upR.f) + fabsf(ctrR.f - ctrL.f));    \
        float mxR = fmaxf(fmaxf(a02.f, a03.f), fmaxf(b02.f, b03.f));           \
        float mnR = (a02.f + a03.f + b02.f + b03.f) * 0.25f;                   \
        oR.f = (dR > lam) ? mxR : mnR;                                         \
    }
    COMP(x) COMP(y) COMP(z) COMP(w)
#undef COMP

    const int pL = (b * OH_ + oh) * OW_ + 2 * j;     // left output pixel
    float4* o4 = (float4*)out;
    o4[pL * C4_ + c4]       = oL;
    o4[(pL + 1) * C4_ + c4] = oR;
}

extern "C" void kernel_launch(void* const* d_in, const int* in_sizes, int n_in,
                              void* d_out, int out_size)
{
    const float* x    = (const float*)d_in[0];
    const float* lamb = (const float*)d_in[1];
    if (n_in >= 2 && in_sizes[0] == 1) {             // guard against metadata order
        x    = (const float*)d_in[1];
        lamb = (const float*)d_in[0];
    }

    const int total = B_ * OH_ * OJ_ * C4_;          // 3,211,264 threads
    const int threads = 256;
    const int blocks = (total + threads - 1) / threads;
    gradpool_kernel<<<blocks, threads>>>(x, lamb, (float*)d_out);
}